// round 6
// baseline (speedup 1.0000x reference)
#include <cuda_runtime.h>
#include <cuda_fp16.h>

#define SEQ    3072
#define HID    1280
#define NHEAD  16
#define HD     80
#define SEGLEN 512
#define NSEG   6
#define QKVN   3840

// ---------------- scratch (no allocations allowed) ----------------
__device__ float  g_qkv[SEQ * QKVN];
__device__ __half g_q[NHEAD * SEQ * HD];       // [h][s][d]
__device__ __half g_k[NHEAD * SEQ * HD];
__device__ __half g_v[NHEAD * SEQ * HD];
__device__ __half g_attn16[SEQ * HID];         // attention output, exact fp16

__device__ __half g_a16[SEQ * HID];            // hidden cast to fp16
__device__ __half g_wqkv16[QKVN * HID];        // w_qkv cast to fp16
__device__ __half g_wpr_hi[HID * HID], g_wpr_lo[HID * HID];

// ---------------- helpers ----------------
__device__ __forceinline__ void cp16(void* dst, const void* src)
{
    unsigned d = (unsigned)__cvta_generic_to_shared(dst);
    asm volatile("cp.async.cg.shared.global [%0], [%1], 16;" :: "r"(d), "l"(src));
}

__device__ __forceinline__ void mma_f16(
    float& c0, float& c1, float& c2, float& c3,
    unsigned a0, unsigned a1, unsigned a2, unsigned a3,
    unsigned b0, unsigned b1)
{
    asm volatile(
        "mma.sync.aligned.m16n8k16.row.col.f32.f16.f16.f32 "
        "{%0,%1,%2,%3}, {%4,%5,%6,%7}, {%8,%9}, {%0,%1,%2,%3};"
        : "+f"(c0), "+f"(c1), "+f"(c2), "+f"(c3)
        : "r"(a0), "r"(a1), "r"(a2), "r"(a3), "r"(b0), "r"(b1));
}

__device__ __forceinline__ void ldsm_x4(unsigned* r, const void* p)
{
    unsigned addr = (unsigned)__cvta_generic_to_shared(p);
    asm volatile("ldmatrix.sync.aligned.m8n8.x4.shared.b16 {%0,%1,%2,%3}, [%4];"
                 : "=r"(r[0]), "=r"(r[1]), "=r"(r[2]), "=r"(r[3]) : "r"(addr));
}
__device__ __forceinline__ void ldsm_x4t(unsigned* r, const void* p)
{
    unsigned addr = (unsigned)__cvta_generic_to_shared(p);
    asm volatile("ldmatrix.sync.aligned.m8n8.x4.trans.shared.b16 {%0,%1,%2,%3}, [%4];"
                 : "=r"(r[0]), "=r"(r[1]), "=r"(r[2]), "=r"(r[3]) : "r"(addr));
}

// ---------------- casts / splits ----------------
__global__ __launch_bounds__(256) void cast16_kernel(
    const float* __restrict__ src, __half* __restrict__ dst, int n4)
{
    int i = blockIdx.x * blockDim.x + threadIdx.x;
    if (i >= n4) return;
    float4 x = ((const float4*)src)[i];
    ((__half2*)dst)[i * 2]     = __floats2half2_rn(x.x, x.y);
    ((__half2*)dst)[i * 2 + 1] = __floats2half2_rn(x.z, x.w);
}

__global__ __launch_bounds__(256) void split16_kernel(
    const float* __restrict__ src,
    __half* __restrict__ hi, __half* __restrict__ lo, int n4)
{
    int i = blockIdx.x * blockDim.x + threadIdx.x;
    if (i >= n4) return;
    float4 x = ((const float4*)src)[i];
    __half h0 = __float2half_rn(x.x), h1 = __float2half_rn(x.y);
    __half h2 = __float2half_rn(x.z), h3 = __float2half_rn(x.w);
    __half l0 = __float2half_rn(x.x - __half2float(h0));
    __half l1 = __float2half_rn(x.y - __half2float(h1));
    __half l2 = __float2half_rn(x.z - __half2float(h2));
    __half l3 = __float2half_rn(x.w - __half2float(h3));
    ((__half2*)hi)[i * 2]     = __halves2half2(h0, h1);
    ((__half2*)hi)[i * 2 + 1] = __halves2half2(h2, h3);
    ((__half2*)lo)[i * 2]     = __halves2half2(l0, l1);
    ((__half2*)lo)[i * 2 + 1] = __halves2half2(l2, l3);
}

// ---------------- GEMM shared config ----------------
#define SPAD 40
#define GSTG (128 * SPAD)

// ---------------- hgemm1: C = A * B^T + bias (single-pass fp16) ----------------
#define GEMM1_SMEM (4 * GSTG * 2)   // 2 arrays x 2 stages x 2B

__global__ __launch_bounds__(256, 2) void hgemm1(
    const __half* __restrict__ A, const __half* __restrict__ B,
    const float* __restrict__ bias, float* __restrict__ C,
    int M, int N, int K)
{
    extern __shared__ __half smg[];
    __half* sA = smg;
    __half* sB = smg + 2 * GSTG;

    const int t    = threadIdx.x;
    const int lane = t & 31;
    const int warp = t >> 5;
    const int mw   = warp >> 2;
    const int nw   = warp & 3;
    const int bm   = blockIdx.y * 128;
    const int bn   = blockIdx.x * 128;

    const int lrow = t >> 1;
    const int lko  = (t & 1) * 16;
    const int soff = lrow * SPAD + lko;

    const size_t gA = (size_t)(bm + lrow) * K + lko;
    const size_t gB = (size_t)(bn + lrow) * K + lko;

    float acc[4][4][4];
#pragma unroll
    for (int i = 0; i < 4; i++)
#pragma unroll
        for (int j = 0; j < 4; j++)
#pragma unroll
            for (int e = 0; e < 4; e++) acc[i][j][e] = 0.0f;

    const int a_row  = (lane & 15);
    const int a_col  = (lane >> 4) * 8;
    const int b_row4 = (lane & 7) + ((lane >> 4) & 1) * 8;
    const int b_col4 = ((lane >> 3) & 1) * 8;

#define PF1(k0, s) do {                                                 \
        int st = (s) * GSTG;                                            \
        cp16(sA + st + soff,     A + gA + (k0));                        \
        cp16(sA + st + soff + 8, A + gA + (k0) + 8);                    \
        cp16(sB + st + soff,     B + gB + (k0));                        \
        cp16(sB + st + soff + 8, B + gB + (k0) + 8);                    \
    } while (0)

    PF1(0, 0);
    asm volatile("cp.async.commit_group;");

    int s = 0;
    for (int k0 = 0; k0 < K; k0 += 32, s ^= 1) {
        if (k0 + 32 < K) {
            PF1(k0 + 32, s ^ 1);
            asm volatile("cp.async.commit_group;");
            asm volatile("cp.async.wait_group 1;");
        } else {
            asm volatile("cp.async.wait_group 0;");
        }
        __syncthreads();

        const int st = s * GSTG;
#pragma unroll
        for (int ks = 0; ks < 32; ks += 16) {
            unsigned af[4][4], bq[2][4];
#pragma unroll
            for (int p = 0; p < 2; p++)
                ldsm_x4(bq[p], &sB[st + (nw * 32 + p * 16 + b_row4) * SPAD + ks + b_col4]);
#pragma unroll
            for (int mt = 0; mt < 4; mt++)
                ldsm_x4(af[mt], &sA[st + (mw * 64 + mt * 16 + a_row) * SPAD + ks + a_col]);
#pragma unroll
            for (int mt = 0; mt < 4; mt++)
#pragma unroll
                for (int p = 0; p < 2; p++) {
                    mma_f16(acc[mt][2*p][0], acc[mt][2*p][1], acc[mt][2*p][2], acc[mt][2*p][3],
                            af[mt][0], af[mt][1], af[mt][2], af[mt][3],
                            bq[p][0], bq[p][1]);
                    mma_f16(acc[mt][2*p+1][0], acc[mt][2*p+1][1], acc[mt][2*p+1][2], acc[mt][2*p+1][3],
                            af[mt][0], af[mt][1], af[mt][2], af[mt][3],
                            bq[p][2], bq[p][3]);
                }
        }
        __syncthreads();
    }

#pragma unroll
    for (int mt = 0; mt < 4; mt++) {
        const int r0 = bm + mw * 64 + mt * 16 + (lane >> 2);
        const int r1 = r0 + 8;
#pragma unroll
        for (int nt = 0; nt < 4; nt++) {
            const int c = bn + nw * 32 + nt * 8 + (lane & 3) * 2;
            const float bv0 = bias[c], bv1 = bias[c + 1];
            float2 o0 = {acc[mt][nt][0] + bv0, acc[mt][nt][1] + bv1};
            float2 o1 = {acc[mt][nt][2] + bv0, acc[mt][nt][3] + bv1};
            *(float2*)&C[(size_t)r0 * N + c] = o0;
            *(float2*)&C[(size_t)r1 * N + c] = o1;
        }
    }
}

// ---------------- hgemm2: C = A * (Bh+Bl)^T + bias (exact) ----------------
#define GEMM2_SMEM (6 * GSTG * 2)

__global__ __launch_bounds__(256, 2) void hgemm2(
    const __half* __restrict__ A,
    const __half* __restrict__ Bh, const __half* __restrict__ Bl,
    const float* __restrict__ bias, float* __restrict__ C,
    int M, int N, int K)
{
    extern __shared__ __half smg[];
    __half* sA  = smg;
    __half* sBh = smg + 2 * GSTG;
    __half* sBl = smg + 4 * GSTG;

    const int t    = threadIdx.x;
    const int lane = t & 31;
    const int warp = t >> 5;
    const int mw   = warp >> 2;
    const int nw   = warp & 3;
    const int bm   = blockIdx.y * 128;
    const int bn   = blockIdx.x * 128;

    const int lrow = t >> 1;
    const int lko  = (t & 1) * 16;
    const int soff = lrow * SPAD + lko;

    const size_t gA = (size_t)(bm + lrow) * K + lko;
    const size_t gB = (size_t)(bn + lrow) * K + lko;

    float acc[4][4][4];
#pragma unroll
    for (int i = 0; i < 4; i++)
#pragma unroll
        for (int j = 0; j < 4; j++)
#pragma unroll
            for (int e = 0; e < 4; e++) acc[i][j][e] = 0.0f;

    const int a_row  = (lane & 15);
    const int a_col  = (lane >> 4) * 8;
    const int b_row4 = (lane & 7) + ((lane >> 4) & 1) * 8;
    const int b_col4 = ((lane >> 3) & 1) * 8;

#define PF2(k0, s) do {                                                 \
        int st = (s) * GSTG;                                            \
        cp16(sA  + st + soff,     A  + gA + (k0));                      \
        cp16(sA  + st + soff + 8, A  + gA + (k0) + 8);                  \
        cp16(sBh + st + soff,     Bh + gB + (k0));                      \
        cp16(sBh + st + soff + 8, Bh + gB + (k0) + 8);                  \
        cp16(sBl + st + soff,     Bl + gB + (k0));                      \
        cp16(sBl + st + soff + 8, Bl + gB + (k0) + 8);                  \
    } while (0)

    PF2(0, 0);
    asm volatile("cp.async.commit_group;");

    int s = 0;
    for (int k0 = 0; k0 < K; k0 += 32, s ^= 1) {
        if (k0 + 32 < K) {
            PF2(k0 + 32, s ^ 1);
            asm volatile("cp.async.commit_group;");
            asm volatile("cp.async.wait_group 1;");
        } else {
            asm volatile("cp.async.wait_group 0;");
        }
        __syncthreads();

        const int st = s * GSTG;
#pragma unroll
        for (int ks = 0; ks < 32; ks += 16) {
            unsigned af[4][4], bh[2][4], bl[2][4];
#pragma unroll
            for (int p = 0; p < 2; p++) {
                const int br = (nw * 32 + p * 16 + b_row4) * SPAD + ks + b_col4;
                ldsm_x4(bh[p], &sBh[st + br]);
                ldsm_x4(bl[p], &sBl[st + br]);
            }
#pragma unroll
            for (int mt = 0; mt < 4; mt++)
                ldsm_x4(af[mt], &sA[st + (mw * 64 + mt * 16 + a_row) * SPAD + ks + a_col]);
#pragma unroll
            for (int mt = 0; mt < 4; mt++)
#pragma unroll
                for (int p = 0; p < 2; p++) {
                    mma_f16(acc[mt][2*p][0], acc[mt][2*p][1], acc[mt][2*p][2], acc[mt][2*p][3],
                            af[mt][0], af[mt][1], af[mt][2], af[mt][3],
                            bh[p][0], bh[p][1]);
                    mma_f16(acc[mt][2*p][0], acc[mt][2*p][1], acc[mt][2*p][2], acc[mt][2*p][3],
                            af[mt][0], af[mt][1], af[mt][2], af[mt][3],
                            bl[p][0], bl[p][1]);
                    mma_f16(acc[mt][2*p+1][0], acc[mt][2*p+1][1], acc[mt][2*p+1][2], acc[mt][2*p+1][3],
                            af[mt][0], af[mt][1], af[mt][2], af[mt][3],
                            bh[p][2], bh[p][3]);
                    mma_f16(acc[mt][2*p+1][0], acc[mt][2*p+1][1], acc[mt][2*p+1][2], acc[mt][2*p+1][3],
                            af[mt][0], af[mt][1], af[mt][2], af[mt][3],
                            bl[p][2], bl[p][3]);
                }
        }
        __syncthreads();
    }

#pragma unroll
    for (int mt = 0; mt < 4; mt++) {
        const int r0 = bm + mw * 64 + mt * 16 + (lane >> 2);
        const int r1 = r0 + 8;
#pragma unroll
        for (int nt = 0; nt < 4; nt++) {
            const int c = bn + nw * 32 + nt * 8 + (lane & 3) * 2;
            const float bv0 = bias[c], bv1 = bias[c + 1];
            float2 o0 = {acc[mt][nt][0] + bv0, acc[mt][nt][1] + bv1};
            float2 o1 = {acc[mt][nt][2] + bv0, acc[mt][nt][3] + bv1};
            *(float2*)&C[(size_t)r0 * N + c] = o0;
            *(float2*)&C[(size_t)r1 * N + c] = o1;
        }
    }
}

// ---------------- RoPE + fp16 cast ----------------
__global__ __launch_bounds__(256) void rope_cast_kernel(
    const float* __restrict__ qkv,
    const float* __restrict__ cosp, const float* __restrict__ sinp,
    __half* __restrict__ q, __half* __restrict__ k, __half* __restrict__ v)
{
    int idx = blockIdx.x * blockDim.x + threadIdx.x;
    if (idx >= SEQ * NHEAD * 40) return;
    int d = idx % 40;
    int h = (idx / 40) % NHEAD;
    int s = idx / (40 * NHEAD);

    float c  = cosp[s * HD + d];
    float sn = sinp[s * HD + d];

    int base = s * QKVN + h * HD + d;
    float q1 = qkv[base],            q2 = qkv[base + 40];
    float k1 = qkv[base + HID],      k2 = qkv[base + HID + 40];
    float v1 = qkv[base + 2 * HID],  v2 = qkv[base + 2 * HID + 40];

    int o = (h * SEQ + s) * HD + d;
    q[o]      = __float2half(q1 * c - q2 * sn);
    q[o + 40] = __float2half(q2 * c + q1 * sn);
    k[o]      = __float2half(k1 * c - k2 * sn);
    k[o + 40] = __float2half(k2 * c + k1 * sn);
    v[o]      = __float2half(v1);
    v[o + 40] = __float2half(v2);
}

// ---------------- attention: fp16 MMA, cp.async double-buffered KV ----------------
#define QPITCH 88
#define SPITCH 520
#define KVTILE (128 * QPITCH)
#define ATTN_SMEM ((KVTILE * 3 + 128 * SPITCH) * 2 + 2 * 128 * 4)

__global__ __launch_bounds__(256) void attn_kernel(
    const __half* __restrict__ q, const __half* __restrict__ k,
    const __half* __restrict__ v, __half* __restrict__ attn_out)
{
    extern __shared__ char smraw[];
    __half* sQ   = (__half*)smraw;                 // [128][QPITCH]
    __half* sKV0 = sQ + KVTILE;
    __half* sKV1 = sKV0 + KVTILE;
    __half* Ss   = sKV1 + KVTILE;                  // [128][SPITCH]
    float*  mrow = (float*)(Ss + 128 * SPITCH);
    float*  lrow = mrow + 128;

    const int tid  = threadIdx.x;
    const int lane = tid & 31;
    const int w    = tid >> 5;
    const int h    = blockIdx.y;
    const int seg  = blockIdx.x >> 2;
    const int qc   = blockIdx.x & 3;
    const int qbase = seg * SEGLEN + qc * 128;
    const int kbase = seg * SEGLEN;
    const float scale = 0.11180339887498949f;

    const int a_row  = (lane & 15);
    const int a_col  = (lane >> 4) * 8;
    const int b_row4 = (lane & 7) + ((lane >> 4) & 1) * 8;
    const int b_col4 = ((lane >> 3) & 1) * 8;

    // async load Q + K tile 0 (group 0)
    for (int i = tid; i < 1280; i += 256) {
        int r = i / 10, c8 = (i % 10) * 8;
        cp16(&sQ[r * QPITCH + c8], &q[(size_t)(h * SEQ + qbase + r) * HD + c8]);
        cp16(&sKV0[r * QPITCH + c8], &k[(size_t)(h * SEQ + kbase + r) * HD + c8]);
    }
    asm volatile("cp.async.commit_group;");

    // ---- pass 1: scores ----
    for (int kt = 0; kt < 4; kt++) {
        __half* cur = (kt & 1) ? sKV1 : sKV0;
        __half* nxt = (kt & 1) ? sKV0 : sKV1;
        if (kt < 3) {
            for (int i = tid; i < 1280; i += 256) {
                int r = i / 10, c8 = (i % 10) * 8;
                cp16(&nxt[r * QPITCH + c8],
                     &k[(size_t)(h * SEQ + kbase + (kt + 1) * 128 + r) * HD + c8]);
            }
            asm volatile("cp.async.commit_group;");
            asm volatile("cp.async.wait_group 1;");
        } else {
            asm volatile("cp.async.wait_group 0;");
        }
        __syncthreads();

        float acc[16][4];
#pragma unroll
        for (int nt = 0; nt < 16; nt++)
#pragma unroll
            for (int e = 0; e < 4; e++) acc[nt][e] = 0.0f;

#pragma unroll
        for (int ks = 0; ks < 80; ks += 16) {
            unsigned af[4];
            ldsm_x4(af, &sQ[(w * 16 + a_row) * QPITCH + ks + a_col]);
#pragma unroll
            for (int p = 0; p < 8; p++) {
                unsigned bq[4];
                ldsm_x4(bq, &cur[(p * 16 + b_row4) * QPITCH + ks + b_col4]);
                mma_f16(acc[2*p][0], acc[2*p][1], acc[2*p][2], acc[2*p][3],
                        af[0], af[1], af[2], af[3], bq[0], bq[1]);
                mma_f16(acc[2*p+1][0], acc[2*p+1][1], acc[2*p+1][2], acc[2*p+1][3],
                        af[0], af[1], af[2], af[3], bq[2], bq[3]);
            }
        }

        const int r0 = w * 16 + (lane >> 2);
#pragma unroll
        for (int nt = 0; nt < 16; nt++) {
            const int c = kt * 128 + nt * 8 + (lane & 3) * 2;
            *(__half2*)&Ss[r0 * SPITCH + c] =
                __floats2half2_rn(acc[nt][0] * scale, acc[nt][1] * scale);
            *(__half2*)&Ss[(r0 + 8) * SPITCH + c] =
                __floats2half2_rn(acc[nt][2] * scale, acc[nt][3] * scale);
        }
        __syncthreads();
    }

    // prefetch V tile 0 (overlaps softmax)
    for (int i = tid; i < 1280; i += 256) {
        int r = i / 10, c8 = (i % 10) * 8;
        cp16(&sKV0[r * QPITCH + c8], &v[(size_t)(h * SEQ + kbase + r) * HD + c8]);
    }
    asm volatile("cp.async.commit_group;");

    // ---- softmax stats ----
    for (int rr = 0; rr < 16; rr++) {
        int r = w * 16 + rr;
        float m = -1e30f;
        for (int c = lane; c < 512; c += 32)
            m = fmaxf(m, __half2float(Ss[r * SPITCH + c]));
#pragma unroll
        for (int o = 16; o; o >>= 1)
            m = fmaxf(m, __shfl_xor_sync(0xffffffffu, m, o));
        float l = 0.0f;
        for (int c = lane; c < 512; c += 32)
            l += expf(__half2float(Ss[r * SPITCH + c]) - m);
#pragma unroll
        for (int o = 16; o; o >>= 1)
            l += __shfl_xor_sync(0xffffffffu, l, o);
        if (lane == 0) { mrow[r] = m; lrow[r] = l; }
    }
    __syncthreads();

    // ---- weights fp16 in place ----
    for (int i = tid; i < 128 * 512; i += 256) {
        int r = i >> 9, c = i & 511;
        float wgt = expf(__half2float(Ss[r * SPITCH + c]) - mrow[r]) / lrow[r];
        Ss[r * SPITCH + c] = __float2half(wgt);
    }

    // ---- pass 2: O = W @ V ----
    float oacc[10][4];
#pragma unroll
    for (int nt = 0; nt < 10; nt++)
#pragma unroll
        for (int e = 0; e < 4; e++) oacc[nt][e] = 0.0f;

    for (int kt = 0; kt < 4; kt++) {
        __half* cur = (kt & 1) ? sKV1 : sKV0;
        __half* nxt = (kt & 1) ? sKV0 : sKV1;
        if (kt < 3) {
            for (int i = tid; i < 1280; i += 256) {
                int r = i / 10, c8 = (i % 10) * 8;
                cp16(&nxt[r * QPITCH + c8],
                     &v[(size_t)(h * SEQ + kbase + (kt + 1) * 128 + r) * HD + c8]);
            }
            asm volatile("cp.async.commit_group;");
            asm volatile("cp.async.wait_group 1;");
        } else {
            asm volatile("cp.async.wait_group 0;");
        }
        __syncthreads();

#pragma unroll
        for (int ks = 0; ks < 8; ks++) {
            unsigned af[4];
            ldsm_x4(af, &Ss[(w * 16 + a_row) * SPITCH + kt * 128 + ks * 16 + a_col]);
#pragma unroll
            for (int p = 0; p < 5; p++) {
                unsigned bq[4];
                ldsm_x4t(bq, &cur[(ks * 16 + (lane & 15)) * QPITCH
                                  + p * 16 + ((lane >> 4) & 1) * 8]);
                mma_f16(oacc[2*p][0], oacc[2*p][1], oacc[2*p][2], oacc[2*p][3],
                        af[0], af[1], af[2], af[3], bq[0], bq[1]);
                mma_f16(oacc[2*p+1][0], oacc[2*p+1][1], oacc[2*p+1][2], oacc[2*p+1][3],
                        af[0], af[1], af[2], af[3], bq[2], bq[3]);
            }
        }
        __syncthreads();
    }

    // write out as fp16 (exact match of reference attn output dtype)
    const int r0 = qbase + w * 16 + (lane >> 2);
#pragma unroll
    for (int nt = 0; nt < 10; nt++) {
        const int c = h * HD + nt * 8 + (lane & 3) * 2;
        *(__half2*)&attn_out[(size_t)r0 * HID + c] =
            __floats2half2_rn(oacc[nt][0], oacc[nt][1]);
        *(__half2*)&attn_out[(size_t)(r0 + 8) * HID + c] =
            __floats2half2_rn(oacc[nt][2], oacc[nt][3]);
    }
}

// ---------------- launch ----------------
extern "C" void kernel_launch(void* const* d_in, const int* in_sizes, int n_in,
                              void* d_out, int out_size)
{
    const float* hidden = (const float*)d_in[0];
    const float* cosp   = (const float*)d_in[1];
    const float* sinp   = (const float*)d_in[2];
    const float* w_qkv  = (const float*)d_in[3];
    const float* b_qkv  = (const float*)d_in[4];
    const float* w_proj = (const float*)d_in[5];
    const float* b_proj = (const float*)d_in[6];
    float* out = (float*)d_out;

    float *qkv_p;
    __half *q_p, *k_p, *v_p, *attn16_p, *a16_p, *wqkv16_p, *wpr_h, *wpr_l;
    cudaGetSymbolAddress((void**)&qkv_p, g_qkv);
    cudaGetSymbolAddress((void**)&q_p, g_q);
    cudaGetSymbolAddress((void**)&k_p, g_k);
    cudaGetSymbolAddress((void**)&v_p, g_v);
    cudaGetSymbolAddress((void**)&attn16_p, g_attn16);
    cudaGetSymbolAddress((void**)&a16_p, g_a16);
    cudaGetSymbolAddress((void**)&wqkv16_p, g_wqkv16);
    cudaGetSymbolAddress((void**)&wpr_h, g_wpr_hi);
    cudaGetSymbolAddress((void**)&wpr_l, g_wpr_lo);

    cudaFuncSetAttribute(attn_kernel,
                         cudaFuncAttributeMaxDynamicSharedMemorySize, ATTN_SMEM);
    cudaFuncSetAttribute(hgemm1,
                         cudaFuncAttributeMaxDynamicSharedMemorySize, GEMM1_SMEM);
    cudaFuncSetAttribute(hgemm2,
                         cudaFuncAttributeMaxDynamicSharedMemorySize, GEMM2_SMEM);

    // 0) casts / splits
    cast16_kernel<<<(SEQ * HID / 4 + 255) / 256, 256>>>(hidden, a16_p, SEQ * HID / 4);
    cast16_kernel<<<(QKVN * HID / 4 + 255) / 256, 256>>>(w_qkv, wqkv16_p, QKVN * HID / 4);
    split16_kernel<<<(HID * HID / 4 + 255) / 256, 256>>>(w_proj, wpr_h, wpr_l, HID * HID / 4);

    // 1) QKV GEMM (single-pass fp16)
    hgemm1<<<dim3(QKVN / 128, SEQ / 128), 256, GEMM1_SMEM>>>(
        a16_p, wqkv16_p, b_qkv, qkv_p, SEQ, QKVN, HID);

    // 2) RoPE + fp16 cast
    rope_cast_kernel<<<(SEQ * NHEAD * 40) / 256, 256>>>(
        qkv_p, cosp, sinp, q_p, k_p, v_p);

    // 3) block-diagonal attention
    attn_kernel<<<dim3(NSEG * 4, NHEAD), 256, ATTN_SMEM>>>(
        q_p, k_p, v_p, attn16_p);

    // 4) proj GEMM (exact: A fp16, B hi/lo)
    hgemm2<<<dim3(HID / 128, SEQ / 128), 256, GEMM2_SMEM>>>(
        attn16_p, wpr_h, wpr_l, b_proj, out, SEQ, HID, HID);
}

// round 8
// speedup vs baseline: 1.4241x; 1.4241x over previous
#include <cuda_runtime.h>
#include <cuda_fp16.h>
#include <cstdint>

#define SEQ    3072
#define HID    1280
#define NHEAD  16
#define HD     80
#define SEGLEN 512
#define NSEG   6
#define QKVN   3840

// ---------------- scratch (no allocations allowed) ----------------
__device__ float  g_qkv[SEQ * QKVN];
__device__ __half g_q[NHEAD * SEQ * HD];       // [h][s][d]
__device__ __half g_k[NHEAD * SEQ * HD];
__device__ __half g_v[NHEAD * SEQ * HD];
__device__ __half g_attn16[SEQ * HID];         // attention output, exact fp16

__device__ __half g_a16[SEQ * HID];            // hidden cast to fp16
__device__ __half g_wqkv16[QKVN * HID];        // w_qkv cast to fp16
__device__ __half g_wpr16[HID * HID];          // w_proj cast to fp16

// ---------------- helpers ----------------
__device__ __forceinline__ void cp16(void* dst, const void* src)
{
    unsigned d = (unsigned)__cvta_generic_to_shared(dst);
    asm volatile("cp.async.cg.shared.global [%0], [%1], 16;" :: "r"(d), "l"(src));
}

__device__ __forceinline__ void mma_f16(
    float& c0, float& c1, float& c2, float& c3,
    unsigned a0, unsigned a1, unsigned a2, unsigned a3,
    unsigned b0, unsigned b1)
{
    asm volatile(
        "mma.sync.aligned.m16n8k16.row.col.f32.f16.f16.f32 "
        "{%0,%1,%2,%3}, {%4,%5,%6,%7}, {%8,%9}, {%0,%1,%2,%3};"
        : "+f"(c0), "+f"(c1), "+f"(c2), "+f"(c3)
        : "r"(a0), "r"(a1), "r"(a2), "r"(a3), "r"(b0), "r"(b1));
}

__device__ __forceinline__ void ldsm_x4(unsigned* r, const void* p)
{
    unsigned addr = (unsigned)__cvta_generic_to_shared(p);
    asm volatile("ldmatrix.sync.aligned.m8n8.x4.shared.b16 {%0,%1,%2,%3}, [%4];"
                 : "=r"(r[0]), "=r"(r[1]), "=r"(r[2]), "=r"(r[3]) : "r"(addr));
}
__device__ __forceinline__ void ldsm_x4t(unsigned* r, const void* p)
{
    unsigned addr = (unsigned)__cvta_generic_to_shared(p);
    asm volatile("ldmatrix.sync.aligned.m8n8.x4.trans.shared.b16 {%0,%1,%2,%3}, [%4];"
                 : "=r"(r[0]), "=r"(r[1]), "=r"(r[2]), "=r"(r[3]) : "r"(addr));
}

__device__ __forceinline__ unsigned packh2(float a, float b)
{
    __half2 h = __floats2half2_rn(a, b);
    return *(unsigned*)&h;
}

// ---------------- casts ----------------
__global__ __launch_bounds__(256) void cast16_kernel(
    const float* __restrict__ src, __half* __restrict__ dst, int n4)
{
    int i = blockIdx.x * blockDim.x + threadIdx.x;
    if (i >= n4) return;
    float4 x = ((const float4*)src)[i];
    ((__half2*)dst)[i * 2]     = __floats2half2_rn(x.x, x.y);
    ((__half2*)dst)[i * 2 + 1] = __floats2half2_rn(x.z, x.w);
}

// ---------------- GEMM config ----------------
#define SPAD 40
#define GSTG (128 * SPAD)
#define GEMM1_SMEM (4 * GSTG * 2)   // 2 arrays x 2 stages x 2B

// ---------------- hgemm1: C = A * B^T + bias (fp16 mma.sync, ~mma ceiling) ----------------
__global__ __launch_bounds__(256, 2) void hgemm1(
    const __half* __restrict__ A, const __half* __restrict__ B,
    const float* __restrict__ bias, float* __restrict__ C,
    int M, int N, int K)
{
    extern __shared__ __half smg[];
    __half* sA = smg;
    __half* sB = smg + 2 * GSTG;

    const int t    = threadIdx.x;
    const int lane = t & 31;
    const int warp = t >> 5;
    const int mw   = warp >> 2;
    const int nw   = warp & 3;
    const int bm   = blockIdx.y * 128;
    const int bn   = blockIdx.x * 128;

    const int lrow = t >> 1;
    const int lko  = (t & 1) * 16;
    const int soff = lrow * SPAD + lko;

    const size_t gA = (size_t)(bm + lrow) * K + lko;
    const size_t gB = (size_t)(bn + lrow) * K + lko;

    float acc[4][4][4];
#pragma unroll
    for (int i = 0; i < 4; i++)
#pragma unroll
        for (int j = 0; j < 4; j++)
#pragma unroll
            for (int e = 0; e < 4; e++) acc[i][j][e] = 0.0f;

    const int a_row  = (lane & 15);
    const int a_col  = (lane >> 4) * 8;
    const int b_row4 = (lane & 7) + ((lane >> 4) & 1) * 8;
    const int b_col4 = ((lane >> 3) & 1) * 8;

#define PF1(k0, s) do {                                                 \
        int st = (s) * GSTG;                                            \
        cp16(sA + st + soff,     A + gA + (k0));                        \
        cp16(sA + st + soff + 8, A + gA + (k0) + 8);                    \
        cp16(sB + st + soff,     B + gB + (k0));                        \
        cp16(sB + st + soff + 8, B + gB + (k0) + 8);                    \
    } while (0)

    PF1(0, 0);
    asm volatile("cp.async.commit_group;");

    int s = 0;
    for (int k0 = 0; k0 < K; k0 += 32, s ^= 1) {
        if (k0 + 32 < K) {
            PF1(k0 + 32, s ^ 1);
            asm volatile("cp.async.commit_group;");
            asm volatile("cp.async.wait_group 1;");
        } else {
            asm volatile("cp.async.wait_group 0;");
        }
        __syncthreads();

        const int st = s * GSTG;
#pragma unroll
        for (int ks = 0; ks < 32; ks += 16) {
            unsigned af[4][4], bq[2][4];
#pragma unroll
            for (int p = 0; p < 2; p++)
                ldsm_x4(bq[p], &sB[st + (nw * 32 + p * 16 + b_row4) * SPAD + ks + b_col4]);
#pragma unroll
            for (int mt = 0; mt < 4; mt++)
                ldsm_x4(af[mt], &sA[st + (mw * 64 + mt * 16 + a_row) * SPAD + ks + a_col]);
#pragma unroll
            for (int mt = 0; mt < 4; mt++)
#pragma unroll
                for (int p = 0; p < 2; p++) {
                    mma_f16(acc[mt][2*p][0], acc[mt][2*p][1], acc[mt][2*p][2], acc[mt][2*p][3],
                            af[mt][0], af[mt][1], af[mt][2], af[mt][3],
                            bq[p][0], bq[p][1]);
                    mma_f16(acc[mt][2*p+1][0], acc[mt][2*p+1][1], acc[mt][2*p+1][2], acc[mt][2*p+1][3],
                            af[mt][0], af[mt][1], af[mt][2], af[mt][3],
                            bq[p][2], bq[p][3]);
                }
        }
        __syncthreads();
    }

#pragma unroll
    for (int mt = 0; mt < 4; mt++) {
        const int r0 = bm + mw * 64 + mt * 16 + (lane >> 2);
        const int r1 = r0 + 8;
#pragma unroll
        for (int nt = 0; nt < 4; nt++) {
            const int c = bn + nw * 32 + nt * 8 + (lane & 3) * 2;
            const float bv0 = bias[c], bv1 = bias[c + 1];
            float2 o0 = {acc[mt][nt][0] + bv0, acc[mt][nt][1] + bv1};
            float2 o1 = {acc[mt][nt][2] + bv0, acc[mt][nt][3] + bv1};
            *(float2*)&C[(size_t)r0 * N + c] = o0;
            *(float2*)&C[(size_t)r1 * N + c] = o1;
        }
    }
}

// ---------------- RoPE + fp16 cast ----------------
__global__ __launch_bounds__(256) void rope_cast_kernel(
    const float* __restrict__ qkv,
    const float* __restrict__ cosp, const float* __restrict__ sinp,
    __half* __restrict__ q, __half* __restrict__ k, __half* __restrict__ v)
{
    int idx = blockIdx.x * blockDim.x + threadIdx.x;
    if (idx >= SEQ * NHEAD * 40) return;
    int d = idx % 40;
    int h = (idx / 40) % NHEAD;
    int s = idx / (40 * NHEAD);

    float c  = cosp[s * HD + d];
    float sn = sinp[s * HD + d];

    int base = s * QKVN + h * HD + d;
    float q1 = qkv[base],            q2 = qkv[base + 40];
    float k1 = qkv[base + HID],      k2 = qkv[base + HID + 40];
    float v1 = qkv[base + 2 * HID],  v2 = qkv[base + 2 * HID + 40];

    int o = (h * SEQ + s) * HD + d;
    q[o]      = __float2half(q1 * c - q2 * sn);
    q[o + 40] = __float2half(q2 * c + q1 * sn);
    k[o]      = __float2half(k1 * c - k2 * sn);
    k[o + 40] = __float2half(k2 * c + k1 * sn);
    v[o]      = __float2half(v1);
    v[o + 40] = __float2half(v2);
}

// ---------------- flash attention: registers-only softmax ----------------
// Block = (head, segment, 128-query chunk). 8 warps x 16 q-rows.
// smem: Q + K double-buffer + V double-buffer (5 tiles of [128][88] fp16).
#define QPITCH 88
#define TILE_H (128 * QPITCH)
#define ATTN_SMEM (5 * TILE_H * 2)

__global__ __launch_bounds__(256) void fattn_kernel(
    const __half* __restrict__ q, const __half* __restrict__ k,
    const __half* __restrict__ v, __half* __restrict__ attn_out)
{
    extern __shared__ char smraw[];
    __half* sQ = (__half*)smraw;
    __half* sK[2] = {sQ + TILE_H,     sQ + 2 * TILE_H};
    __half* sV[2] = {sQ + 3 * TILE_H, sQ + 4 * TILE_H};

    const int tid  = threadIdx.x;
    const int lane = tid & 31;
    const int w    = tid >> 5;
    const int h    = blockIdx.y;
    const int seg  = blockIdx.x >> 2;
    const int qc   = blockIdx.x & 3;
    const int qbase = seg * SEGLEN + qc * 128;
    const int kbase = seg * SEGLEN;
    const float scale = 0.11180339887498949f;   // 80^-0.5

    const int a_row  = (lane & 15);
    const int a_col  = (lane >> 4) * 8;
    const int b_row4 = (lane & 7) + ((lane >> 4) & 1) * 8;
    const int b_col4 = ((lane >> 3) & 1) * 8;

    // preload Q + K0 + V0 (one group)
    for (int i = tid; i < 1280; i += 256) {
        int r = i / 10, c8 = (i % 10) * 8;
        cp16(&sQ[r * QPITCH + c8],    &q[(size_t)(h * SEQ + qbase + r) * HD + c8]);
        cp16(&sK[0][r * QPITCH + c8], &k[(size_t)(h * SEQ + kbase + r) * HD + c8]);
        cp16(&sV[0][r * QPITCH + c8], &v[(size_t)(h * SEQ + kbase + r) * HD + c8]);
    }
    asm volatile("cp.async.commit_group;");

    float m0 = -1e30f, m1 = -1e30f, l0 = 0.0f, l1 = 0.0f;
    float oacc[10][4];
#pragma unroll
    for (int nt = 0; nt < 10; nt++)
#pragma unroll
        for (int e = 0; e < 4; e++) oacc[nt][e] = 0.0f;

    for (int kt = 0; kt < 4; kt++) {
        asm volatile("cp.async.wait_group 0;");
        __syncthreads();
        if (kt < 3) {
            const int nb = (kt + 1) & 1;
            for (int i = tid; i < 1280; i += 256) {
                int r = i / 10, c8 = (i % 10) * 8;
                cp16(&sK[nb][r * QPITCH + c8],
                     &k[(size_t)(h * SEQ + kbase + (kt + 1) * 128 + r) * HD + c8]);
                cp16(&sV[nb][r * QPITCH + c8],
                     &v[(size_t)(h * SEQ + kbase + (kt + 1) * 128 + r) * HD + c8]);
            }
            asm volatile("cp.async.commit_group;");
        }
        __half* cK = sK[kt & 1];
        __half* cV = sV[kt & 1];

        // two 64-col halves (keeps score regs at 8x4)
#pragma unroll
        for (int hv = 0; hv < 2; hv++) {
            float s[8][4];
#pragma unroll
            for (int nt = 0; nt < 8; nt++)
#pragma unroll
                for (int e = 0; e < 4; e++) s[nt][e] = 0.0f;

#pragma unroll
            for (int ks = 0; ks < 80; ks += 16) {
                unsigned af[4];
                ldsm_x4(af, &sQ[(w * 16 + a_row) * QPITCH + ks + a_col]);
#pragma unroll
                for (int p = 0; p < 4; p++) {
                    unsigned bq[4];
                    ldsm_x4(bq, &cK[(hv * 64 + p * 16 + b_row4) * QPITCH + ks + b_col4]);
                    mma_f16(s[2*p][0], s[2*p][1], s[2*p][2], s[2*p][3],
                            af[0], af[1], af[2], af[3], bq[0], bq[1]);
                    mma_f16(s[2*p+1][0], s[2*p+1][1], s[2*p+1][2], s[2*p+1][3],
                            af[0], af[1], af[2], af[3], bq[2], bq[3]);
                }
            }

            // scale + tile max (rows r = lane>>2 and r+8)
            float mx0 = -1e30f, mx1 = -1e30f;
#pragma unroll
            for (int nt = 0; nt < 8; nt++) {
                s[nt][0] *= scale; s[nt][1] *= scale;
                s[nt][2] *= scale; s[nt][3] *= scale;
                mx0 = fmaxf(mx0, fmaxf(s[nt][0], s[nt][1]));
                mx1 = fmaxf(mx1, fmaxf(s[nt][2], s[nt][3]));
            }
            mx0 = fmaxf(mx0, __shfl_xor_sync(0xffffffffu, mx0, 1));
            mx0 = fmaxf(mx0, __shfl_xor_sync(0xffffffffu, mx0, 2));
            mx1 = fmaxf(mx1, __shfl_xor_sync(0xffffffffu, mx1, 1));
            mx1 = fmaxf(mx1, __shfl_xor_sync(0xffffffffu, mx1, 2));

            const float mn0 = fmaxf(m0, mx0), mn1 = fmaxf(m1, mx1);
            const float al0 = __expf(m0 - mn0), al1 = __expf(m1 - mn1);

            // P = exp(s - m'), packed fp16 A-fragments; row sums
            float sum0 = 0.0f, sum1 = 0.0f;
            unsigned pk[8][2];
#pragma unroll
            for (int nt = 0; nt < 8; nt++) {
                float p0 = __expf(s[nt][0] - mn0);
                float p1 = __expf(s[nt][1] - mn0);
                float p2 = __expf(s[nt][2] - mn1);
                float p3 = __expf(s[nt][3] - mn1);
                sum0 += p0 + p1;
                sum1 += p2 + p3;
                pk[nt][0] = packh2(p0, p1);   // row r,   k-cols 2c,2c+1
                pk[nt][1] = packh2(p2, p3);   // row r+8
            }
            sum0 += __shfl_xor_sync(0xffffffffu, sum0, 1);
            sum0 += __shfl_xor_sync(0xffffffffu, sum0, 2);
            sum1 += __shfl_xor_sync(0xffffffffu, sum1, 1);
            sum1 += __shfl_xor_sync(0xffffffffu, sum1, 2);

            l0 = l0 * al0 + sum0;
            l1 = l1 * al1 + sum1;
            m0 = mn0; m1 = mn1;

            // rescale O
#pragma unroll
            for (int nt = 0; nt < 10; nt++) {
                oacc[nt][0] *= al0; oacc[nt][1] *= al0;
                oacc[nt][2] *= al1; oacc[nt][3] *= al1;
            }

            // O += P @ V  (P fragments straight from registers)
#pragma unroll
            for (int j = 0; j < 4; j++) {
                const unsigned fa0 = pk[2*j][0],   fa1 = pk[2*j][1];
                const unsigned fa2 = pk[2*j+1][0], fa3 = pk[2*j+1][1];
#pragma unroll
                for (int p = 0; p < 5; p++) {
                    unsigned bq[4];
                    ldsm_x4t(bq, &cV[(hv * 64 + j * 16 + (lane & 15)) * QPITCH
                                     + p * 16 + ((lane >> 4) & 1) * 8]);
                    mma_f16(oacc[2*p][0], oacc[2*p][1], oacc[2*p][2], oacc[2*p][3],
                            fa0, fa1, fa2, fa3, bq[0], bq[1]);
                    mma_f16(oacc[2*p+1][0], oacc[2*p+1][1], oacc[2*p+1][2], oacc[2*p+1][3],
                            fa0, fa1, fa2, fa3, bq[2], bq[3]);
                }
            }
        }
    }

    // epilogue: normalize and store fp16
    const float inv0 = 1.0f / l0, inv1 = 1.0f / l1;
    const int r0 = qbase + w * 16 + (lane >> 2);
#pragma unroll
    for (int nt = 0; nt < 10; nt++) {
        const int c = h * HD + nt * 8 + (lane & 3) * 2;
        *(__half2*)&attn_out[(size_t)r0 * HID + c] =
            __floats2half2_rn(oacc[nt][0] * inv0, oacc[nt][1] * inv0);
        *(__half2*)&attn_out[(size_t)(r0 + 8) * HID + c] =
            __floats2half2_rn(oacc[nt][2] * inv1, oacc[nt][3] * inv1);
    }
}

// ---------------- launch ----------------
extern "C" void kernel_launch(void* const* d_in, const int* in_sizes, int n_in,
                              void* d_out, int out_size)
{
    const float* hidden = (const float*)d_in[0];
    const float* cosp   = (const float*)d_in[1];
    const float* sinp   = (const float*)d_in[2];
    const float* w_qkv  = (const float*)d_in[3];
    const float* b_qkv  = (const float*)d_in[4];
    const float* w_proj = (const float*)d_in[5];
    const float* b_proj = (const float*)d_in[6];
    float* out = (float*)d_out;

    float *qkv_p;
    __half *q_p, *k_p, *v_p, *attn16_p, *a16_p, *wqkv16_p, *wpr16_p;
    cudaGetSymbolAddress((void**)&qkv_p, g_qkv);
    cudaGetSymbolAddress((void**)&q_p, g_q);
    cudaGetSymbolAddress((void**)&k_p, g_k);
    cudaGetSymbolAddress((void**)&v_p, g_v);
    cudaGetSymbolAddress((void**)&attn16_p, g_attn16);
    cudaGetSymbolAddress((void**)&a16_p, g_a16);
    cudaGetSymbolAddress((void**)&wqkv16_p, g_wqkv16);
    cudaGetSymbolAddress((void**)&wpr16_p, g_wpr16);

    cudaFuncSetAttribute(fattn_kernel,
                         cudaFuncAttributeMaxDynamicSharedMemorySize, ATTN_SMEM);
    cudaFuncSetAttribute(hgemm1,
                         cudaFuncAttributeMaxDynamicSharedMemorySize, GEMM1_SMEM);

    // 0) casts
    cast16_kernel<<<(SEQ * HID / 4 + 255) / 256, 256>>>(hidden, a16_p, SEQ * HID / 4);
    cast16_kernel<<<(QKVN * HID / 4 + 255) / 256, 256>>>(w_qkv, wqkv16_p, QKVN * HID / 4);
    cast16_kernel<<<(HID * HID / 4 + 255) / 256, 256>>>(w_proj, wpr16_p, HID * HID / 4);

    // 1) QKV GEMM (fp16 mma.sync)
    hgemm1<<<dim3(QKVN / 128, SEQ / 128), 256, GEMM1_SMEM>>>(
        a16_p, wqkv16_p, b_qkv, qkv_p, SEQ, QKVN, HID);

    // 2) RoPE + fp16 cast
    rope_cast_kernel<<<(SEQ * NHEAD * 40) / 256, 256>>>(
        qkv_p, cosp, sinp, q_p, k_p, v_p);

    // 3) flash attention (block-diagonal)
    fattn_kernel<<<dim3(NSEG * 4, NHEAD), 256, ATTN_SMEM>>>(
        q_p, k_p, v_p, attn16_p);

    // 4) proj GEMM (fp16 single-pass)
    hgemm1<<<dim3(HID / 128, SEQ / 128), 256, GEMM1_SMEM>>>(
        attn16_p, wpr16_p, b_proj, out, SEQ, HID, HID);
}

// round 9
// speedup vs baseline: 1.7654x; 1.2396x over previous
#include <cuda_runtime.h>
#include <cuda_fp16.h>
#include <cstdint>

#define SEQ    3072
#define HID    1280
#define NHEAD  16
#define HD     80
#define SEGLEN 512
#define NSEG   6
#define QKVN   3840

// ---------------- scratch (no allocations allowed) ----------------
__device__ __half g_qkv16[SEQ * QKVN];         // qkv, fp16 (GEMM writes fp16 directly)
__device__ __half g_q[NHEAD * SEQ * HD];       // [h][s][d]
__device__ __half g_k[NHEAD * SEQ * HD];
__device__ __half g_v[NHEAD * SEQ * HD];
__device__ __half g_attn16[SEQ * HID];         // attention output, exact fp16

__device__ __half g_a16[SEQ * HID];            // hidden cast to fp16
__device__ __half g_wqkv16[QKVN * HID];        // w_qkv cast to fp16
__device__ __half g_wpr16[HID * HID];          // w_proj cast to fp16

// ---------------- helpers ----------------
__device__ __forceinline__ void cp16(void* dst, const void* src)
{
    unsigned d = (unsigned)__cvta_generic_to_shared(dst);
    asm volatile("cp.async.cg.shared.global [%0], [%1], 16;" :: "r"(d), "l"(src));
}

__device__ __forceinline__ void mma_f16(
    float& c0, float& c1, float& c2, float& c3,
    unsigned a0, unsigned a1, unsigned a2, unsigned a3,
    unsigned b0, unsigned b1)
{
    asm volatile(
        "mma.sync.aligned.m16n8k16.row.col.f32.f16.f16.f32 "
        "{%0,%1,%2,%3}, {%4,%5,%6,%7}, {%8,%9}, {%0,%1,%2,%3};"
        : "+f"(c0), "+f"(c1), "+f"(c2), "+f"(c3)
        : "r"(a0), "r"(a1), "r"(a2), "r"(a3), "r"(b0), "r"(b1));
}

__device__ __forceinline__ void ldsm_x4(unsigned* r, const void* p)
{
    unsigned addr = (unsigned)__cvta_generic_to_shared(p);
    asm volatile("ldmatrix.sync.aligned.m8n8.x4.shared.b16 {%0,%1,%2,%3}, [%4];"
                 : "=r"(r[0]), "=r"(r[1]), "=r"(r[2]), "=r"(r[3]) : "r"(addr));
}
__device__ __forceinline__ void ldsm_x4t(unsigned* r, const void* p)
{
    unsigned addr = (unsigned)__cvta_generic_to_shared(p);
    asm volatile("ldmatrix.sync.aligned.m8n8.x4.trans.shared.b16 {%0,%1,%2,%3}, [%4];"
                 : "=r"(r[0]), "=r"(r[1]), "=r"(r[2]), "=r"(r[3]) : "r"(addr));
}

__device__ __forceinline__ unsigned packh2(float a, float b)
{
    __half2 h = __floats2half2_rn(a, b);
    return *(unsigned*)&h;
}

// ---------------- casts ----------------
__global__ __launch_bounds__(256) void cast16_kernel(
    const float* __restrict__ src, __half* __restrict__ dst, int n4)
{
    int i = blockIdx.x * blockDim.x + threadIdx.x;
    if (i >= n4) return;
    float4 x = ((const float4*)src)[i];
    ((__half2*)dst)[i * 2]     = __floats2half2_rn(x.x, x.y);
    ((__half2*)dst)[i * 2 + 1] = __floats2half2_rn(x.z, x.w);
}

// ---------------- hgemm1: C = A * B^T + bias; BK=64, 2-stage cp.async ----------------
// OUT16=1: fp16 output; OUT16=0: fp32 output.
#define SPAD 72
#define GSTG (128 * SPAD)
#define GEMM_SMEM (4 * GSTG * 2)   // 2 arrays x 2 stages x 2B = 73728

template<int OUT16>
__global__ __launch_bounds__(256, 2) void hgemm1(
    const __half* __restrict__ A, const __half* __restrict__ B,
    const float* __restrict__ bias, void* __restrict__ Cv,
    int M, int N, int K)
{
    extern __shared__ __half smg[];
    __half* sA = smg;
    __half* sB = smg + 2 * GSTG;

    const int t    = threadIdx.x;
    const int lane = t & 31;
    const int warp = t >> 5;
    const int mw   = warp >> 2;
    const int nw   = warp & 3;
    const int bm   = blockIdx.y * 128;
    const int bn   = blockIdx.x * 128;

    float acc[4][4][4];
#pragma unroll
    for (int i = 0; i < 4; i++)
#pragma unroll
        for (int j = 0; j < 4; j++)
#pragma unroll
            for (int e = 0; e < 4; e++) acc[i][j][e] = 0.0f;

    const int a_row  = (lane & 15);
    const int a_col  = (lane >> 4) * 8;
    const int b_row4 = (lane & 7) + ((lane >> 4) & 1) * 8;
    const int b_col4 = ((lane >> 3) & 1) * 8;

#define PFG(k0, s) do {                                                  \
        const int st = (s) * GSTG;                                       \
        for (int i = t; i < 1024; i += 256) {                            \
            int r = i >> 3, c8 = (i & 7) * 8;                            \
            cp16(sA + st + r * SPAD + c8, A + (size_t)(bm + r) * K + (k0) + c8); \
            cp16(sB + st + r * SPAD + c8, B + (size_t)(bn + r) * K + (k0) + c8); \
        }                                                                \
        asm volatile("cp.async.commit_group;");                          \
    } while (0)

    PFG(0, 0);

    int s = 0;
    for (int k0 = 0; k0 < K; k0 += 64, s ^= 1) {
        if (k0 + 64 < K) {
            PFG(k0 + 64, s ^ 1);
            asm volatile("cp.async.wait_group 1;");
        } else {
            asm volatile("cp.async.wait_group 0;");
        }
        __syncthreads();

        const int st = s * GSTG;
#pragma unroll
        for (int ks = 0; ks < 64; ks += 16) {
            unsigned af[4][4], bq[2][4];
#pragma unroll
            for (int p = 0; p < 2; p++)
                ldsm_x4(bq[p], &sB[st + (nw * 32 + p * 16 + b_row4) * SPAD + ks + b_col4]);
#pragma unroll
            for (int mt = 0; mt < 4; mt++)
                ldsm_x4(af[mt], &sA[st + (mw * 64 + mt * 16 + a_row) * SPAD + ks + a_col]);
#pragma unroll
            for (int mt = 0; mt < 4; mt++)
#pragma unroll
                for (int p = 0; p < 2; p++) {
                    mma_f16(acc[mt][2*p][0], acc[mt][2*p][1], acc[mt][2*p][2], acc[mt][2*p][3],
                            af[mt][0], af[mt][1], af[mt][2], af[mt][3],
                            bq[p][0], bq[p][1]);
                    mma_f16(acc[mt][2*p+1][0], acc[mt][2*p+1][1], acc[mt][2*p+1][2], acc[mt][2*p+1][3],
                            af[mt][0], af[mt][1], af[mt][2], af[mt][3],
                            bq[p][2], bq[p][3]);
                }
        }
        __syncthreads();
    }

#pragma unroll
    for (int mt = 0; mt < 4; mt++) {
        const int r0 = bm + mw * 64 + mt * 16 + (lane >> 2);
        const int r1 = r0 + 8;
#pragma unroll
        for (int nt = 0; nt < 4; nt++) {
            const int c = bn + nw * 32 + nt * 8 + (lane & 3) * 2;
            const float bv0 = bias[c], bv1 = bias[c + 1];
            if (OUT16) {
                __half* C = (__half*)Cv;
                *(__half2*)&C[(size_t)r0 * N + c] =
                    __floats2half2_rn(acc[mt][nt][0] + bv0, acc[mt][nt][1] + bv1);
                *(__half2*)&C[(size_t)r1 * N + c] =
                    __floats2half2_rn(acc[mt][nt][2] + bv0, acc[mt][nt][3] + bv1);
            } else {
                float* C = (float*)Cv;
                float2 o0 = {acc[mt][nt][0] + bv0, acc[mt][nt][1] + bv1};
                float2 o1 = {acc[mt][nt][2] + bv0, acc[mt][nt][3] + bv1};
                *(float2*)&C[(size_t)r0 * N + c] = o0;
                *(float2*)&C[(size_t)r1 * N + c] = o1;
            }
        }
    }
}

// ---------------- RoPE (fp16 in, fp16 out) ----------------
__global__ __launch_bounds__(256) void rope_cast_kernel(
    const __half* __restrict__ qkv,
    const float* __restrict__ cosp, const float* __restrict__ sinp,
    __half* __restrict__ q, __half* __restrict__ k, __half* __restrict__ v)
{
    int idx = blockIdx.x * blockDim.x + threadIdx.x;
    if (idx >= SEQ * NHEAD * 40) return;
    int d = idx % 40;
    int h = (idx / 40) % NHEAD;
    int s = idx / (40 * NHEAD);

    float c  = cosp[s * HD + d];
    float sn = sinp[s * HD + d];

    int base = s * QKVN + h * HD + d;
    float q1 = __half2float(qkv[base]);
    float q2 = __half2float(qkv[base + 40]);
    float k1 = __half2float(qkv[base + HID]);
    float k2 = __half2float(qkv[base + HID + 40]);

    int o = (h * SEQ + s) * HD + d;
    q[o]      = __float2half(q1 * c - q2 * sn);
    q[o + 40] = __float2half(q2 * c + q1 * sn);
    k[o]      = __float2half(k1 * c - k2 * sn);
    k[o + 40] = __float2half(k2 * c + k1 * sn);
    v[o]      = qkv[base + 2 * HID];
    v[o + 40] = qkv[base + 2 * HID + 40];
}

// ---------------- flash attention (unchanged from round 8) ----------------
#define QPITCH 88
#define TILE_H (128 * QPITCH)
#define ATTN_SMEM (5 * TILE_H * 2)

__global__ __launch_bounds__(256) void fattn_kernel(
    const __half* __restrict__ q, const __half* __restrict__ k,
    const __half* __restrict__ v, __half* __restrict__ attn_out)
{
    extern __shared__ char smraw[];
    __half* sQ = (__half*)smraw;
    __half* sK[2] = {sQ + TILE_H,     sQ + 2 * TILE_H};
    __half* sV[2] = {sQ + 3 * TILE_H, sQ + 4 * TILE_H};

    const int tid  = threadIdx.x;
    const int lane = tid & 31;
    const int w    = tid >> 5;
    const int h    = blockIdx.y;
    const int seg  = blockIdx.x >> 2;
    const int qc   = blockIdx.x & 3;
    const int qbase = seg * SEGLEN + qc * 128;
    const int kbase = seg * SEGLEN;
    const float scale = 0.11180339887498949f;   // 80^-0.5

    const int a_row  = (lane & 15);
    const int a_col  = (lane >> 4) * 8;
    const int b_row4 = (lane & 7) + ((lane >> 4) & 1) * 8;
    const int b_col4 = ((lane >> 3) & 1) * 8;

    for (int i = tid; i < 1280; i += 256) {
        int r = i / 10, c8 = (i % 10) * 8;
        cp16(&sQ[r * QPITCH + c8],    &q[(size_t)(h * SEQ + qbase + r) * HD + c8]);
        cp16(&sK[0][r * QPITCH + c8], &k[(size_t)(h * SEQ + kbase + r) * HD + c8]);
        cp16(&sV[0][r * QPITCH + c8], &v[(size_t)(h * SEQ + kbase + r) * HD + c8]);
    }
    asm volatile("cp.async.commit_group;");

    float m0 = -1e30f, m1 = -1e30f, l0 = 0.0f, l1 = 0.0f;
    float oacc[10][4];
#pragma unroll
    for (int nt = 0; nt < 10; nt++)
#pragma unroll
        for (int e = 0; e < 4; e++) oacc[nt][e] = 0.0f;

    for (int kt = 0; kt < 4; kt++) {
        asm volatile("cp.async.wait_group 0;");
        __syncthreads();
        if (kt < 3) {
            const int nb = (kt + 1) & 1;
            for (int i = tid; i < 1280; i += 256) {
                int r = i / 10, c8 = (i % 10) * 8;
                cp16(&sK[nb][r * QPITCH + c8],
                     &k[(size_t)(h * SEQ + kbase + (kt + 1) * 128 + r) * HD + c8]);
                cp16(&sV[nb][r * QPITCH + c8],
                     &v[(size_t)(h * SEQ + kbase + (kt + 1) * 128 + r) * HD + c8]);
            }
            asm volatile("cp.async.commit_group;");
        }
        __half* cK = sK[kt & 1];
        __half* cV = sV[kt & 1];

#pragma unroll
        for (int hv = 0; hv < 2; hv++) {
            float s[8][4];
#pragma unroll
            for (int nt = 0; nt < 8; nt++)
#pragma unroll
                for (int e = 0; e < 4; e++) s[nt][e] = 0.0f;

#pragma unroll
            for (int ks = 0; ks < 80; ks += 16) {
                unsigned af[4];
                ldsm_x4(af, &sQ[(w * 16 + a_row) * QPITCH + ks + a_col]);
#pragma unroll
                for (int p = 0; p < 4; p++) {
                    unsigned bq[4];
                    ldsm_x4(bq, &cK[(hv * 64 + p * 16 + b_row4) * QPITCH + ks + b_col4]);
                    mma_f16(s[2*p][0], s[2*p][1], s[2*p][2], s[2*p][3],
                            af[0], af[1], af[2], af[3], bq[0], bq[1]);
                    mma_f16(s[2*p+1][0], s[2*p+1][1], s[2*p+1][2], s[2*p+1][3],
                            af[0], af[1], af[2], af[3], bq[2], bq[3]);
                }
            }

            float mx0 = -1e30f, mx1 = -1e30f;
#pragma unroll
            for (int nt = 0; nt < 8; nt++) {
                s[nt][0] *= scale; s[nt][1] *= scale;
                s[nt][2] *= scale; s[nt][3] *= scale;
                mx0 = fmaxf(mx0, fmaxf(s[nt][0], s[nt][1]));
                mx1 = fmaxf(mx1, fmaxf(s[nt][2], s[nt][3]));
            }
            mx0 = fmaxf(mx0, __shfl_xor_sync(0xffffffffu, mx0, 1));
            mx0 = fmaxf(mx0, __shfl_xor_sync(0xffffffffu, mx0, 2));
            mx1 = fmaxf(mx1, __shfl_xor_sync(0xffffffffu, mx1, 1));
            mx1 = fmaxf(mx1, __shfl_xor_sync(0xffffffffu, mx1, 2));

            const float mn0 = fmaxf(m0, mx0), mn1 = fmaxf(m1, mx1);
            const float al0 = __expf(m0 - mn0), al1 = __expf(m1 - mn1);

            float sum0 = 0.0f, sum1 = 0.0f;
            unsigned pk[8][2];
#pragma unroll
            for (int nt = 0; nt < 8; nt++) {
                float p0 = __expf(s[nt][0] - mn0);
                float p1 = __expf(s[nt][1] - mn0);
                float p2 = __expf(s[nt][2] - mn1);
                float p3 = __expf(s[nt][3] - mn1);
                sum0 += p0 + p1;
                sum1 += p2 + p3;
                pk[nt][0] = packh2(p0, p1);
                pk[nt][1] = packh2(p2, p3);
            }
            sum0 += __shfl_xor_sync(0xffffffffu, sum0, 1);
            sum0 += __shfl_xor_sync(0xffffffffu, sum0, 2);
            sum1 += __shfl_xor_sync(0xffffffffu, sum1, 1);
            sum1 += __shfl_xor_sync(0xffffffffu, sum1, 2);

            l0 = l0 * al0 + sum0;
            l1 = l1 * al1 + sum1;
            m0 = mn0; m1 = mn1;

#pragma unroll
            for (int nt = 0; nt < 10; nt++) {
                oacc[nt][0] *= al0; oacc[nt][1] *= al0;
                oacc[nt][2] *= al1; oacc[nt][3] *= al1;
            }

#pragma unroll
            for (int j = 0; j < 4; j++) {
                const unsigned fa0 = pk[2*j][0],   fa1 = pk[2*j][1];
                const unsigned fa2 = pk[2*j+1][0], fa3 = pk[2*j+1][1];
#pragma unroll
                for (int p = 0; p < 5; p++) {
                    unsigned bq[4];
                    ldsm_x4t(bq, &cV[(hv * 64 + j * 16 + (lane & 15)) * QPITCH
                                     + p * 16 + ((lane >> 4) & 1) * 8]);
                    mma_f16(oacc[2*p][0], oacc[2*p][1], oacc[2*p][2], oacc[2*p][3],
                            fa0, fa1, fa2, fa3, bq[0], bq[1]);
                    mma_f16(oacc[2*p+1][0], oacc[2*p+1][1], oacc[2*p+1][2], oacc[2*p+1][3],
                            fa0, fa1, fa2, fa3, bq[2], bq[3]);
                }
            }
        }
    }

    const float inv0 = 1.0f / l0, inv1 = 1.0f / l1;
    const int r0 = qbase + w * 16 + (lane >> 2);
#pragma unroll
    for (int nt = 0; nt < 10; nt++) {
        const int c = h * HD + nt * 8 + (lane & 3) * 2;
        *(__half2*)&attn_out[(size_t)r0 * HID + c] =
            __floats2half2_rn(oacc[nt][0] * inv0, oacc[nt][1] * inv0);
        *(__half2*)&attn_out[(size_t)(r0 + 8) * HID + c] =
            __floats2half2_rn(oacc[nt][2] * inv1, oacc[nt][3] * inv1);
    }
}

// ---------------- launch ----------------
extern "C" void kernel_launch(void* const* d_in, const int* in_sizes, int n_in,
                              void* d_out, int out_size)
{
    const float* hidden = (const float*)d_in[0];
    const float* cosp   = (const float*)d_in[1];
    const float* sinp   = (const float*)d_in[2];
    const float* w_qkv  = (const float*)d_in[3];
    const float* b_qkv  = (const float*)d_in[4];
    const float* w_proj = (const float*)d_in[5];
    const float* b_proj = (const float*)d_in[6];

    __half *qkv16_p, *q_p, *k_p, *v_p, *attn16_p, *a16_p, *wqkv16_p, *wpr16_p;
    cudaGetSymbolAddress((void**)&qkv16_p, g_qkv16);
    cudaGetSymbolAddress((void**)&q_p, g_q);
    cudaGetSymbolAddress((void**)&k_p, g_k);
    cudaGetSymbolAddress((void**)&v_p, g_v);
    cudaGetSymbolAddress((void**)&attn16_p, g_attn16);
    cudaGetSymbolAddress((void**)&a16_p, g_a16);
    cudaGetSymbolAddress((void**)&wqkv16_p, g_wqkv16);
    cudaGetSymbolAddress((void**)&wpr16_p, g_wpr16);

    cudaFuncSetAttribute(fattn_kernel,
                         cudaFuncAttributeMaxDynamicSharedMemorySize, ATTN_SMEM);
    cudaFuncSetAttribute(hgemm1<0>,
                         cudaFuncAttributeMaxDynamicSharedMemorySize, GEMM_SMEM);
    cudaFuncSetAttribute(hgemm1<1>,
                         cudaFuncAttributeMaxDynamicSharedMemorySize, GEMM_SMEM);

    // 0) casts
    cast16_kernel<<<(SEQ * HID / 4 + 255) / 256, 256>>>(hidden, a16_p, SEQ * HID / 4);
    cast16_kernel<<<(QKVN * HID / 4 + 255) / 256, 256>>>(w_qkv, wqkv16_p, QKVN * HID / 4);
    cast16_kernel<<<(HID * HID / 4 + 255) / 256, 256>>>(w_proj, wpr16_p, HID * HID / 4);

    // 1) QKV GEMM (fp16 mma.sync, fp16 output)
    hgemm1<1><<<dim3(QKVN / 128, SEQ / 128), 256, GEMM_SMEM>>>(
        a16_p, wqkv16_p, b_qkv, qkv16_p, SEQ, QKVN, HID);

    // 2) RoPE (fp16 in/out)
    rope_cast_kernel<<<(SEQ * NHEAD * 40) / 256, 256>>>(
        qkv16_p, cosp, sinp, q_p, k_p, v_p);

    // 3) flash attention (block-diagonal)
    fattn_kernel<<<dim3(NSEG * 4, NHEAD), 256, ATTN_SMEM>>>(
        q_p, k_p, v_p, attn16_p);

    // 4) proj GEMM (fp16 mma.sync, fp32 output)
    hgemm1<0><<<dim3(HID / 128, SEQ / 128), 256, GEMM_SMEM>>>(
        attn16_p, wpr16_p, b_proj, d_out, SEQ, HID, HID);
}